// round 12
// baseline (speedup 1.0000x reference)
#include <cuda_runtime.h>
#include <cuda_fp16.h>
#include <cstdint>

#define S_LEN 2048
#define DMODEL 1024
#define NHEADS 16
#define DK 64
#define BATCH 2
#define BH (BATCH * NHEADS)
#define MROWS (BATCH * S_LEN)   // 4096
#define NTILE 32                // 2048/64 key tiles per row
#define NQT 16                  // 2048/128 q tiles per row

// ---------------- scratch (device globals; no allocation allowed) ----------
__device__ float g_ctx[BH * S_LEN * DK];
__device__ float g_m[BH * S_LEN];           // log2-domain row max
__device__ float g_l[BH * S_LEN];           // row sumexp
__device__ __half g_wh[4 * DMODEL * DMODEL];    // weights [n][k] f16
__device__ __half g_qhf[BH * S_LEN * DK];       // [bh][s][dk]
__device__ __half g_khf[BH * S_LEN * DK];       // [bh][s][dk]
__device__ __half g_vtf[BH * DK * S_LEN];       // [bh][dk][s]  (transposed)

// ---------------- primitives ------------------------------------------------
__device__ __forceinline__ uint32_t smem_u32(const void* p) {
    uint32_t a;
    asm("{ .reg .u64 t; cvta.to.shared.u64 t, %1; cvt.u32.u64 %0, t; }" : "=r"(a) : "l"(p));
    return a;
}
__device__ __forceinline__ void ldmx4(uint32_t* r, uint32_t addr) {
    asm volatile("ldmatrix.sync.aligned.m8n8.x4.shared.b16 {%0,%1,%2,%3}, [%4];"
                 : "=r"(r[0]), "=r"(r[1]), "=r"(r[2]), "=r"(r[3]) : "r"(addr));
}
__device__ __forceinline__ void mma16816h(float* c, const uint32_t* a, const uint32_t* b) {
    asm volatile(
        "mma.sync.aligned.m16n8k16.row.col.f32.f16.f16.f32 "
        "{%0,%1,%2,%3}, {%4,%5,%6,%7}, {%8,%9}, {%0,%1,%2,%3};"
        : "+f"(c[0]), "+f"(c[1]), "+f"(c[2]), "+f"(c[3])
        : "r"(a[0]), "r"(a[1]), "r"(a[2]), "r"(a[3]), "r"(b[0]), "r"(b[1]));
}
__device__ __forceinline__ uint32_t pack_f16x2(float lo, float hi) {
    uint32_t d;
    asm("cvt.rn.f16x2.f32 %0, %1, %2;" : "=r"(d) : "f"(hi), "f"(lo));
    return d;
}
__device__ __forceinline__ uint32_t f2h2(float a, float b) {
    __half2 h = __floats2half2_rn(a, b);
    return *(uint32_t*)&h;
}
__device__ __forceinline__ void cp16(uint32_t saddr, const void* g) {
    asm volatile("cp.async.cg.shared.global [%0], [%1], 16;" :: "r"(saddr), "l"(g));
}
__device__ __forceinline__ void cp_commit() {
    asm volatile("cp.async.commit_group;" ::: "memory");
}
template <int N>
__device__ __forceinline__ void cp_wait() {
    asm volatile("cp.async.wait_group %0;" :: "n"(N) : "memory");
}

// ==========================================================================
// Weight conversion (fp32 [k][n] -> f16 [n][k], all 4 weights in one launch)
// ==========================================================================
__global__ __launch_bounds__(256) void conv_w4(
    const float* __restrict__ W0, const float* __restrict__ W1,
    const float* __restrict__ W2, const float* __restrict__ W3,
    __half* __restrict__ Wh)
{
    __shared__ float t[32][33];
    const int z = blockIdx.z;
    const float* W = (z == 0) ? W0 : (z == 1) ? W1 : (z == 2) ? W2 : W3;
    __half* dst = Wh + (size_t)z * DMODEL * DMODEL;
    const int bx = blockIdx.x * 32;
    const int by = blockIdx.y * 32;
    const int tx = threadIdx.x & 31;
    const int ty = threadIdx.x >> 5;
#pragma unroll
    for (int i = 0; i < 32; i += 8)
        t[ty + i][tx] = W[(size_t)(by + ty + i) * DMODEL + bx + tx];
    __syncthreads();
#pragma unroll
    for (int i = 0; i < 32; i += 8)
        dst[(size_t)(bx + ty + i) * DMODEL + by + tx] = __float2half(t[tx][ty + i]);
}

// ==========================================================================
// HMMA fp16 GEMM with fused fp32->f16 A conversion. 2 CTAs/SM.
// ==========================================================================
#define KC 32
#define NCH (DMODEL / KC)    // 32
#define LDS_STRIDE 40

struct DenseA {
    const float* base;
    __device__ __forceinline__ const float* operator()(int r, int k) const {
        return base + (size_t)r * DMODEL + k;
    }
};
struct CtxA {
    const float* ctx;
    int m0;
    __device__ __forceinline__ const float* operator()(int r, int k) const {
        int m = m0 + r;
        int b = m >> 11, s = m & 2047, h = k >> 6, d = k & 63;
        return ctx + (((size_t)(b * 16 + h)) * S_LEN + s) * DK + d;
    }
};

template <class AF>
__device__ __forceinline__ void gemm_mainloop(
    AF aptr, const __half* Brow,
    __half (*As)[128 * LDS_STRIDE], __half (*Bs)[128 * LDS_STRIDE],
    int tid, int lane, int warp_m, int warp_n, float acc[2][8][4])
{
    const int r0 = tid >> 2, c0 = (tid & 3) * 8;
    const int r1 = r0 + 64;

    {
        const float* a0p = aptr(r0, c0);
        const float* a1p = aptr(r1, c0);
        float4 fa0 = *(const float4*)a0p, fa0b = *(const float4*)(a0p + 4);
        float4 fa1 = *(const float4*)a1p, fa1b = *(const float4*)(a1p + 4);
        uint4 b0 = *(const uint4*)(Brow + (size_t)r0 * DMODEL + c0);
        uint4 b1 = *(const uint4*)(Brow + (size_t)r1 * DMODEL + c0);
        uint4 ua0 = make_uint4(f2h2(fa0.x, fa0.y), f2h2(fa0.z, fa0.w),
                               f2h2(fa0b.x, fa0b.y), f2h2(fa0b.z, fa0b.w));
        uint4 ua1 = make_uint4(f2h2(fa1.x, fa1.y), f2h2(fa1.z, fa1.w),
                               f2h2(fa1b.x, fa1b.y), f2h2(fa1b.z, fa1b.w));
        *(uint4*)(As[0] + r0 * LDS_STRIDE + c0) = ua0;
        *(uint4*)(As[0] + r1 * LDS_STRIDE + c0) = ua1;
        *(uint4*)(Bs[0] + r0 * LDS_STRIDE + c0) = b0;
        *(uint4*)(Bs[0] + r1 * LDS_STRIDE + c0) = b1;
    }
    __syncthreads();

    for (int c = 0; c < NCH; c++) {
        const int cur = c & 1, nxt = cur ^ 1;
        float4 fa0, fa0b, fa1, fa1b;
        uint4 pb0, pb1;
        if (c + 1 < NCH) {
            const int ko = (c + 1) * KC;
            const float* a0p = aptr(r0, ko + c0);
            const float* a1p = aptr(r1, ko + c0);
            fa0 = *(const float4*)a0p; fa0b = *(const float4*)(a0p + 4);
            fa1 = *(const float4*)a1p; fa1b = *(const float4*)(a1p + 4);
            pb0 = *(const uint4*)(Brow + (size_t)r0 * DMODEL + ko + c0);
            pb1 = *(const uint4*)(Brow + (size_t)r1 * DMODEL + ko + c0);
        }

        const uint32_t sa = smem_u32(As[cur]);
        const uint32_t sbm = smem_u32(Bs[cur]);
#pragma unroll
        for (int kk2 = 0; kk2 < 2; kk2++) {
            const int kk = kk2 * 16;
            uint32_t af[2][4];
#pragma unroll
            for (int mi = 0; mi < 2; mi++) {
                uint32_t addr = sa + ((warp_m + mi * 16 + (lane & 15)) * LDS_STRIDE
                                      + kk + (lane >> 4) * 8) * 2;
                ldmx4(af[mi], addr);
            }
            uint32_t bf[8][2];
#pragma unroll
            for (int ni2 = 0; ni2 < 4; ni2++) {
                uint32_t rr[4];
                uint32_t addr = sbm + ((warp_n + ni2 * 16 + (lane & 7) + 8 * ((lane >> 3) & 1))
                                       * LDS_STRIDE + kk + (lane >> 4) * 8) * 2;
                ldmx4(rr, addr);
                bf[2 * ni2][0] = rr[0]; bf[2 * ni2 + 1][0] = rr[1];
                bf[2 * ni2][1] = rr[2]; bf[2 * ni2 + 1][1] = rr[3];
            }
#pragma unroll
            for (int mi = 0; mi < 2; mi++)
#pragma unroll
                for (int ni = 0; ni < 8; ni++)
                    mma16816h(acc[mi][ni], af[mi], bf[ni]);
        }

        if (c + 1 < NCH) {
            uint4 ua0 = make_uint4(f2h2(fa0.x, fa0.y), f2h2(fa0.z, fa0.w),
                                   f2h2(fa0b.x, fa0b.y), f2h2(fa0b.z, fa0b.w));
            uint4 ua1 = make_uint4(f2h2(fa1.x, fa1.y), f2h2(fa1.z, fa1.w),
                                   f2h2(fa1b.x, fa1b.y), f2h2(fa1b.z, fa1b.w));
            *(uint4*)(As[nxt] + r0 * LDS_STRIDE + c0) = ua0;
            *(uint4*)(As[nxt] + r1 * LDS_STRIDE + c0) = ua1;
            *(uint4*)(Bs[nxt] + r0 * LDS_STRIDE + c0) = pb0;
            *(uint4*)(Bs[nxt] + r1 * LDS_STRIDE + c0) = pb1;
        }
        __syncthreads();
    }
}

__global__ __launch_bounds__(256, 2) void gemm_qkv(
    const float* __restrict__ q, const float* __restrict__ k,
    const float* __restrict__ v, const __half* __restrict__ Wh,
    const float* __restrict__ bq, const float* __restrict__ bk,
    const float* __restrict__ bv,
    __half* __restrict__ qhf, __half* __restrict__ khf, __half* __restrict__ vtf)
{
    __shared__ __half As[2][128 * LDS_STRIDE];
    __shared__ __half Bs[2][128 * LDS_STRIDE];

    const int tid = threadIdx.x;
    const int wid = tid >> 5, lane = tid & 31;
    const int z = blockIdx.z;
    const int m0 = blockIdx.y * 128, n0 = blockIdx.x * 128;
    const int warp_m = (wid & 3) * 32;
    const int warp_n = (wid >> 2) * 64;

    const float* X = (z == 0) ? q : (z == 1) ? k : v;
    const __half* Brow = Wh + ((size_t)z * DMODEL + n0) * DMODEL;
    const float* bias = (z == 0) ? bq : (z == 1) ? bk : bv;
    __half* Ch = (z == 0) ? qhf : (z == 1) ? khf : vtf;

    float acc[2][8][4];
#pragma unroll
    for (int mi = 0; mi < 2; mi++)
#pragma unroll
        for (int ni = 0; ni < 8; ni++)
#pragma unroll
            for (int j = 0; j < 4; j++) acc[mi][ni][j] = 0.f;

    DenseA ap{X + (size_t)m0 * DMODEL};
    gemm_mainloop(ap, Brow, As, Bs, tid, lane, warp_m, warp_n, acc);

#pragma unroll
    for (int ni = 0; ni < 8; ni++) {
        const int n = n0 + warp_n + ni * 8 + (lane & 3) * 2;
        const float bv0 = __ldg(&bias[n]);
        const float bv1 = __ldg(&bias[n + 1]);
#pragma unroll
        for (int mi = 0; mi < 2; mi++) {
#pragma unroll
            for (int half = 0; half < 2; half++) {
                const int m = m0 + warp_m + mi * 16 + (lane >> 2) + half * 8;
                float ox = acc[mi][ni][2 * half] + bv0;
                float oy = acc[mi][ni][2 * half + 1] + bv1;
                int b = m >> 11, s = m & 2047;
                int h = n >> 6, d = n & 63;
                if (z < 2) {
                    *(__half2*)&Ch[(((size_t)(b * 16 + h)) * S_LEN + s) * DK + d] =
                        __floats2half2_rn(ox, oy);
                } else {
                    size_t vb = ((size_t)(b * 16 + h) * DK + d) * S_LEN + s;
                    Ch[vb] = __float2half(ox);
                    Ch[vb + S_LEN] = __float2half(oy);
                }
            }
        }
    }
}

__global__ __launch_bounds__(256, 2) void gemm_out(
    const float* __restrict__ ctx, const __half* __restrict__ Wh,
    const float* __restrict__ bias, float* __restrict__ C)
{
    __shared__ __half As[2][128 * LDS_STRIDE];
    __shared__ __half Bs[2][128 * LDS_STRIDE];

    const int tid = threadIdx.x;
    const int wid = tid >> 5, lane = tid & 31;
    const int m0 = blockIdx.y * 128, n0 = blockIdx.x * 128;
    const int warp_m = (wid & 3) * 32;
    const int warp_n = (wid >> 2) * 64;

    const __half* Brow = Wh + (size_t)n0 * DMODEL;

    float acc[2][8][4];
#pragma unroll
    for (int mi = 0; mi < 2; mi++)
#pragma unroll
        for (int ni = 0; ni < 8; ni++)
#pragma unroll
            for (int j = 0; j < 4; j++) acc[mi][ni][j] = 0.f;

    CtxA ap{ctx, m0};
    gemm_mainloop(ap, Brow, As, Bs, tid, lane, warp_m, warp_n, acc);

#pragma unroll
    for (int ni = 0; ni < 8; ni++) {
        const int n = n0 + warp_n + ni * 8 + (lane & 3) * 2;
        const float bv0 = __ldg(&bias[n]);
        const float bv1 = __ldg(&bias[n + 1]);
#pragma unroll
        for (int mi = 0; mi < 2; mi++) {
#pragma unroll
            for (int half = 0; half < 2; half++) {
                const int m = m0 + warp_m + mi * 16 + (lane >> 2) + half * 8;
                *(float2*)&C[(size_t)m * DMODEL + n] =
                    make_float2(acc[mi][ni][2 * half] + bv0,
                                acc[mi][ni][2 * half + 1] + bv1);
            }
        }
    }
}

// ==========================================================================
// Attention pass 1: per-row m, l. Paired q-tiles (qt, 15-qt) per CTA for
// perfect causal load balance; cp.async double-buffered K; 3 CTAs/SM.
// ==========================================================================
#define ATT_STRIDE 72
#define SC_LOG2E 0.18033688011112042f   // log2(e)/sqrt(64)

__global__ __launch_bounds__(256, 3) void attn_pass1(
    const __half* __restrict__ qhf, const __half* __restrict__ khf,
    float* __restrict__ gm, float* __restrict__ gl)
{
    __shared__ __half Qs[128 * ATT_STRIDE];
    __shared__ __half Ks[2][64 * ATT_STRIDE];

    const int tid = threadIdx.x, lane = tid & 31, wid = tid >> 5;
    const int bh = blockIdx.x;
    const int qw0 = wid * 16;
    const size_t qbase = (size_t)bh * S_LEN * DK;
    const int lr = tid >> 2, lg = (tid & 3) * 2;
    const uint32_t sQ = smem_u32(Qs);

#pragma unroll 1
    for (int ph = 0; ph < 2; ph++) {
        const int qt = ph ? (int)blockIdx.y : (NQT - 1 - (int)blockIdx.y);
        const int i0 = qt * 128;

        __syncthreads();   // protect Qs reuse across phases
#pragma unroll
        for (int it = 0; it < 4; it++) {
            int idx = tid + it * 256;
            int r = idx >> 3, g = idx & 7;
            *(uint4*)&Qs[r * ATT_STRIDE + g * 8] =
                *(const uint4*)&qhf[qbase + (size_t)(i0 + r) * DK + g * 8];
        }

        const int ntiles = 2 * qt + 2;
#pragma unroll
        for (int h = 0; h < 2; h++)
            cp16(smem_u32(&Ks[0][lr * ATT_STRIDE + (lg + h) * 8]),
                 &khf[qbase + (size_t)lr * DK + (lg + h) * 8]);
        cp_commit();

        float m2[2] = {-1e30f, -1e30f};
        float l[2] = {0.f, 0.f};
        const int rg0 = i0 + qw0 + (lane >> 2);

        for (int jt = 0; jt < ntiles; jt++) {
            const int cur = jt & 1;
            if (jt + 1 < ntiles) {
                const int j1 = (jt + 1) * 64;
#pragma unroll
                for (int h = 0; h < 2; h++)
                    cp16(smem_u32(&Ks[cur ^ 1][lr * ATT_STRIDE + (lg + h) * 8]),
                         &khf[qbase + (size_t)(j1 + lr) * DK + (lg + h) * 8]);
                cp_commit();
                cp_wait<1>();
            } else {
                cp_wait<0>();
            }
            __syncthreads();

            const int j0 = jt * 64;
            const uint32_t sK = smem_u32(Ks[cur]);

            float sacc[8][4];
#pragma unroll
            for (int ni = 0; ni < 8; ni++)
#pragma unroll
                for (int j = 0; j < 4; j++) sacc[ni][j] = 0.f;

#pragma unroll
            for (int t = 0; t < 4; t++) {
                const int ko = t * 16;
                uint32_t af[4];
                ldmx4(af, sQ + ((qw0 + (lane & 15)) * ATT_STRIDE + ko + (lane >> 4) * 8) * 2);
                uint32_t bf[8][2];
#pragma unroll
                for (int nb = 0; nb < 4; nb++) {
                    uint32_t r[4];
                    ldmx4(r, sK + ((nb * 16 + (lane & 7) + 8 * ((lane >> 3) & 1)) * ATT_STRIDE
                                   + ko + (lane >> 4) * 8) * 2);
                    bf[2 * nb][0] = r[0]; bf[2 * nb + 1][0] = r[1];
                    bf[2 * nb][1] = r[2]; bf[2 * nb + 1][1] = r[3];
                }
#pragma unroll
                for (int ni = 0; ni < 8; ni++) mma16816h(sacc[ni], af, bf[ni]);
            }

            float mx0 = -1e30f, mx1 = -1e30f;
            const bool masked = (jt >= ntiles - 2);
#pragma unroll
            for (int ni = 0; ni < 8; ni++) {
#pragma unroll
                for (int j = 0; j < 4; j++) sacc[ni][j] *= SC_LOG2E;
                if (masked) {
                    int cg = j0 + ni * 8 + (lane & 3) * 2;
                    if (cg > rg0)     sacc[ni][0] = -1e30f;
                    if (cg + 1 > rg0) sacc[ni][1] = -1e30f;
                    if (cg > rg0 + 8)     sacc[ni][2] = -1e30f;
                    if (cg + 1 > rg0 + 8) sacc[ni][3] = -1e30f;
                }
                mx0 = fmaxf(mx0, fmaxf(sacc[ni][0], sacc[ni][1]));
                mx1 = fmaxf(mx1, fmaxf(sacc[ni][2], sacc[ni][3]));
            }
#pragma unroll
            for (int o = 1; o < 4; o <<= 1) {
                mx0 = fmaxf(mx0, __shfl_xor_sync(0xffffffffu, mx0, o));
                mx1 = fmaxf(mx1, __shfl_xor_sync(0xffffffffu, mx1, o));
            }
            const float mn0 = fmaxf(m2[0], mx0), mn1 = fmaxf(m2[1], mx1);
            float ts0 = 0.f, ts1 = 0.f;
#pragma unroll
            for (int ni = 0; ni < 8; ni++) {
                ts0 += exp2f(sacc[ni][0] - mn0) + exp2f(sacc[ni][1] - mn0);
                ts1 += exp2f(sacc[ni][2] - mn1) + exp2f(sacc[ni][3] - mn1);
            }
#pragma unroll
            for (int o = 1; o < 4; o <<= 1) {
                ts0 += __shfl_xor_sync(0xffffffffu, ts0, o);
                ts1 += __shfl_xor_sync(0xffffffffu, ts1, o);
            }
            l[0] = l[0] * exp2f(m2[0] - mn0) + ts0;
            l[1] = l[1] * exp2f(m2[1] - mn1) + ts1;
            m2[0] = mn0; m2[1] = mn1;
            __syncthreads();
        }

        if ((lane & 3) == 0) {
            gm[bh * S_LEN + rg0] = m2[0];      gm[bh * S_LEN + rg0 + 8] = m2[1];
            gl[bh * S_LEN + rg0] = l[0];       gl[bh * S_LEN + rg0 + 8] = l[1];
        }
    }
}

// ==========================================================================
// Attention pass 2: paired q-tiles; P fragments stay in registers; cp.async
// K/V double buffer; attn = p/l written directly. 2 CTAs/SM.
// ==========================================================================
#define ATT2_SMEM ((128 * ATT_STRIDE + 4 * 64 * ATT_STRIDE) * 2)   // 55296

__global__ __launch_bounds__(256, 2) void attn_pass2(
    const __half* __restrict__ qhf, const __half* __restrict__ khf,
    const __half* __restrict__ vtf,
    const float* __restrict__ gm, const float* __restrict__ gl,
    float* __restrict__ attn, float* __restrict__ ctx)
{
    extern __shared__ __half sh[];
    __half* Qs = sh;                            // [128][72]
    __half* Kb[2] = { sh + 128 * ATT_STRIDE,
                      sh + (128 + 64) * ATT_STRIDE };
    __half* Vb[2] = { sh + (128 + 128) * ATT_STRIDE,
                      sh + (128 + 192) * ATT_STRIDE };

    const int tid = threadIdx.x, lane = tid & 31, wid = tid >> 5;
    const int bh = blockIdx.x;
    const int qw0 = wid * 16;
    const size_t qbase = (size_t)bh * S_LEN * DK;
    const int lr = tid >> 2, lg = (tid & 3) * 2;
    const uint32_t sQ = smem_u32(Qs);

#pragma unroll 1
    for (int ph = 0; ph < 2; ph++) {
        const int qt = ph ? (int)blockIdx.y : (NQT - 1 - (int)blockIdx.y);
        const int i0 = qt * 128;

        __syncthreads();   // protect Qs/K/V reuse across phases
#pragma unroll
        for (int it = 0; it < 4; it++) {
            int idx = tid + it * 256;
            int r = idx >> 3, g = idx & 7;
            *(uint4*)&Qs[r * ATT_STRIDE + g * 8] =
                *(const uint4*)&qhf[qbase + (size_t)(i0 + r) * DK + g * 8];
        }

        const int rg0 = i0 + qw0 + (lane >> 2);
        const float mf0 = gm[bh * S_LEN + rg0], mf1 = gm[bh * S_LEN + rg0 + 8];
        const float li0 = 1.f / gl[bh * S_LEN + rg0], li1 = 1.f / gl[bh * S_LEN + rg0 + 8];

        float cacc[8][4];
#pragma unroll
        for (int ni = 0; ni < 8; ni++)
#pragma unroll
            for (int j = 0; j < 4; j++) cacc[ni][j] = 0.f;

        const int ntiles = 2 * qt + 2;

        // preload tile 0 (K + V)
#pragma unroll
        for (int h = 0; h < 2; h++) {
            cp16(smem_u32(&Kb[0][lr * ATT_STRIDE + (lg + h) * 8]),
                 &khf[qbase + (size_t)lr * DK + (lg + h) * 8]);
            cp16(smem_u32(&Vb[0][lr * ATT_STRIDE + (lg + h) * 8]),
                 &vtf[((size_t)bh * DK + lr) * S_LEN + (lg + h) * 8]);
        }
        cp_commit();

        for (int jt = 0; jt < ntiles; jt++) {
            const int cur = jt & 1;
            if (jt + 1 < ntiles) {
                const int j1 = (jt + 1) * 64;
#pragma unroll
                for (int h = 0; h < 2; h++) {
                    cp16(smem_u32(&Kb[cur ^ 1][lr * ATT_STRIDE + (lg + h) * 8]),
                         &khf[qbase + (size_t)(j1 + lr) * DK + (lg + h) * 8]);
                    cp16(smem_u32(&Vb[cur ^ 1][lr * ATT_STRIDE + (lg + h) * 8]),
                         &vtf[((size_t)bh * DK + lr) * S_LEN + j1 + (lg + h) * 8]);
                }
                cp_commit();
                cp_wait<1>();
            } else {
                cp_wait<0>();
            }
            __syncthreads();

            const int j0 = jt * 64;
            const uint32_t sK = smem_u32(Kb[cur]);
            const uint32_t sV = smem_u32(Vb[cur]);

            // ---- QK^T ----
            float sacc[8][4];
#pragma unroll
            for (int ni = 0; ni < 8; ni++)
#pragma unroll
                for (int j = 0; j < 4; j++) sacc[ni][j] = 0.f;

#pragma unroll
            for (int t = 0; t < 4; t++) {
                const int ko = t * 16;
                uint32_t af[4];
                ldmx4(af, sQ + ((qw0 + (lane & 15)) * ATT_STRIDE + ko + (lane >> 4) * 8) * 2);
                uint32_t bf[8][2];
#pragma unroll
                for (int nb = 0; nb < 4; nb++) {
                    uint32_t r[4];
                    ldmx4(r, sK + ((nb * 16 + (lane & 7) + 8 * ((lane >> 3) & 1)) * ATT_STRIDE
                                   + ko + (lane >> 4) * 8) * 2);
                    bf[2 * nb][0] = r[0]; bf[2 * nb + 1][0] = r[1];
                    bf[2 * nb][1] = r[2]; bf[2 * nb + 1][1] = r[3];
                }
#pragma unroll
                for (int ni = 0; ni < 8; ni++) mma16816h(sacc[ni], af, bf[ni]);
            }

            // ---- softmax: p fp32 -> attn store + packed P fragments ----
            const bool masked = (jt >= ntiles - 2);
            uint32_t pp[8][2];
#pragma unroll
            for (int ni = 0; ni < 8; ni++) {
                const int c = ni * 8 + (lane & 3) * 2;
                float s0 = sacc[ni][0] * SC_LOG2E, s1 = sacc[ni][1] * SC_LOG2E;
                float s2 = sacc[ni][2] * SC_LOG2E, s3 = sacc[ni][3] * SC_LOG2E;
                if (masked) {
                    int cg = j0 + c;
                    if (cg > rg0)         s0 = -1e30f;
                    if (cg + 1 > rg0)     s1 = -1e30f;
                    if (cg > rg0 + 8)     s2 = -1e30f;
                    if (cg + 1 > rg0 + 8) s3 = -1e30f;
                }
                float p0 = exp2f(s0 - mf0), p1 = exp2f(s1 - mf0);
                float p2 = exp2f(s2 - mf1), p3 = exp2f(s3 - mf1);
                pp[ni][0] = pack_f16x2(p0, p1);
                pp[ni][1] = pack_f16x2(p2, p3);
                if (attn) {
                    *(float2*)&attn[((size_t)bh * S_LEN + rg0) * S_LEN + j0 + c] =
                        make_float2(p0 * li0, p1 * li0);
                    *(float2*)&attn[((size_t)bh * S_LEN + rg0 + 8) * S_LEN + j0 + c] =
                        make_float2(p2 * li1, p3 * li1);
                }
            }

            // ---- PV: ctx += P @ V, P fragments from registers ----
#pragma unroll
            for (int t = 0; t < 4; t++) {
                const int ko = t * 16;
                uint32_t af[4] = { pp[2 * t][0], pp[2 * t][1],
                                   pp[2 * t + 1][0], pp[2 * t + 1][1] };
                uint32_t bf[8][2];
#pragma unroll
                for (int nb = 0; nb < 4; nb++) {
                    uint32_t r[4];
                    ldmx4(r, sV + ((nb * 16 + (lane & 7) + 8 * ((lane >> 3) & 1)) * ATT_STRIDE
                                   + ko + (lane >> 4) * 8) * 2);
                    bf[2 * nb][0] = r[0]; bf[2 * nb + 1][0] = r[1];
                    bf[2 * nb][1] = r[2]; bf[2 * nb + 1][1] = r[3];
                }
#pragma unroll
                for (int ni = 0; ni < 8; ni++) mma16816h(cacc[ni], af, bf[ni]);
            }
            __syncthreads();
        }

        // zero-fill the never-visited upper-triangle tiles of attn
        if (attn) {
            for (int jt = ntiles; jt < NTILE; jt++) {
                const int j0 = jt * 64;
#pragma unroll
                for (int it = 0; it < 8; it++) {
                    int idx = tid + it * 256;
                    int r = idx >> 4, c4 = (idx & 15) << 2;
                    *(float4*)&attn[((size_t)bh * S_LEN + i0 + r) * S_LEN + j0 + c4] =
                        make_float4(0.f, 0.f, 0.f, 0.f);
                }
            }
        }

        // epilogue: ctx = cacc / l
#pragma unroll
        for (int ni = 0; ni < 8; ni++) {
            const int d = ni * 8 + (lane & 3) * 2;
            *(float2*)&ctx[qbase + (size_t)rg0 * DK + d] =
                make_float2(cacc[ni][0] * li0, cacc[ni][1] * li0);
            *(float2*)&ctx[qbase + (size_t)(rg0 + 8) * DK + d] =
                make_float2(cacc[ni][2] * li1, cacc[ni][3] * li1);
        }
    }
}

// ==========================================================================
// host launch
// ==========================================================================
extern "C" void kernel_launch(void* const* d_in, const int* in_sizes, int n_in,
                              void* d_out, int out_size)
{
    const float* q  = (const float*)d_in[0];
    const float* k  = (const float*)d_in[1];
    const float* v  = (const float*)d_in[2];
    const float* wq = (const float*)d_in[4];
    const float* bq = (const float*)d_in[5];
    const float* wk = (const float*)d_in[6];
    const float* bk = (const float*)d_in[7];
    const float* wv = (const float*)d_in[8];
    const float* bv = (const float*)d_in[9];
    const float* wo = (const float*)d_in[10];
    const float* bo = (const float*)d_in[11];

    float *ctx, *gm, *gl;
    __half *wh, *qhf, *khf, *vtf;
    cudaGetSymbolAddress((void**)&ctx, g_ctx);
    cudaGetSymbolAddress((void**)&gm, g_m);
    cudaGetSymbolAddress((void**)&gl, g_l);
    cudaGetSymbolAddress((void**)&wh, g_wh);
    cudaGetSymbolAddress((void**)&qhf, g_qhf);
    cudaGetSymbolAddress((void**)&khf, g_khf);
    cudaGetSymbolAddress((void**)&vtf, g_vtf);

    float* outbuf = (float*)d_out;
    float* out_ptr = nullptr;
    float* attn_ptr = nullptr;
    const long long OUT_N  = (long long)BATCH * S_LEN * DMODEL;
    const long long ATTN_N = (long long)BH * S_LEN * S_LEN;
    long long osz = (long long)out_size;
    if (osz >= OUT_N + ATTN_N)      { out_ptr = outbuf; attn_ptr = outbuf + OUT_N; }
    else if (osz == OUT_N)          { out_ptr = outbuf; }
    else                            { attn_ptr = outbuf; }

    cudaFuncSetAttribute(attn_pass2, cudaFuncAttributeMaxDynamicSharedMemorySize, ATT2_SMEM);

    dim3 wgrid(32, 32, 4);
    conv_w4<<<wgrid, 256>>>(wq, wk, wv, wo, wh);

    dim3 ggrid(DMODEL / 128, MROWS / 128, 3);   // (8, 32, 3)
    gemm_qkv<<<ggrid, 256>>>(q, k, v, wh, bq, bk, bv, qhf, khf, vtf);

    dim3 agrid(BH, NQT / 2);                    // (32, 8) — paired q-tiles
    attn_pass1<<<agrid, 256>>>(qhf, khf, gm, gl);
    attn_pass2<<<agrid, 256, ATT2_SMEM>>>(qhf, khf, vtf, gm, gl, attn_ptr, ctx);

    if (out_ptr) {
        dim3 ogrid(DMODEL / 128, MROWS / 128);
        gemm_out<<<ogrid, 256>>>(ctx, wh + 3 * (size_t)DMODEL * DMODEL, bo, out_ptr);
    }
}

// round 13
// speedup vs baseline: 1.0483x; 1.0483x over previous
#include <cuda_runtime.h>
#include <cuda_fp16.h>
#include <cstdint>

#define S_LEN 2048
#define DMODEL 1024
#define NHEADS 16
#define DK 64
#define BATCH 2
#define BH (BATCH * NHEADS)
#define MROWS (BATCH * S_LEN)   // 4096
#define NTILE 32                // 2048/64 key tiles per row

// ---------------- scratch (device globals; no allocation allowed) ----------
__device__ float g_ctx[BH * S_LEN * DK];
__device__ float g_m[BH * S_LEN];           // log2-domain row max
__device__ float g_l[BH * S_LEN];           // row sumexp
__device__ __half g_wh[4 * DMODEL * DMODEL];    // weights [n][k] f16
__device__ __half g_qhf[BH * S_LEN * DK];       // [bh][s][dk]
__device__ __half g_khf[BH * S_LEN * DK];       // [bh][s][dk]
__device__ __half g_vtf[BH * DK * S_LEN];       // [bh][dk][s]  (transposed)

// ---------------- primitives ------------------------------------------------
__device__ __forceinline__ uint32_t smem_u32(const void* p) {
    uint32_t a;
    asm("{ .reg .u64 t; cvta.to.shared.u64 t, %1; cvt.u32.u64 %0, t; }" : "=r"(a) : "l"(p));
    return a;
}
__device__ __forceinline__ void ldmx4(uint32_t* r, uint32_t addr) {
    asm volatile("ldmatrix.sync.aligned.m8n8.x4.shared.b16 {%0,%1,%2,%3}, [%4];"
                 : "=r"(r[0]), "=r"(r[1]), "=r"(r[2]), "=r"(r[3]) : "r"(addr));
}
__device__ __forceinline__ void mma16816h(float* c, const uint32_t* a, const uint32_t* b) {
    asm volatile(
        "mma.sync.aligned.m16n8k16.row.col.f32.f16.f16.f32 "
        "{%0,%1,%2,%3}, {%4,%5,%6,%7}, {%8,%9}, {%0,%1,%2,%3};"
        : "+f"(c[0]), "+f"(c[1]), "+f"(c[2]), "+f"(c[3])
        : "r"(a[0]), "r"(a[1]), "r"(a[2]), "r"(a[3]), "r"(b[0]), "r"(b[1]));
}
__device__ __forceinline__ uint32_t pack_f16x2(float lo, float hi) {
    uint32_t d;
    asm("cvt.rn.f16x2.f32 %0, %1, %2;" : "=r"(d) : "f"(hi), "f"(lo));
    return d;
}
__device__ __forceinline__ uint32_t f2h2(float a, float b) {
    __half2 h = __floats2half2_rn(a, b);
    return *(uint32_t*)&h;
}
__device__ __forceinline__ void cp16(uint32_t saddr, const void* g) {
    asm volatile("cp.async.cg.shared.global [%0], [%1], 16;" :: "r"(saddr), "l"(g));
}
__device__ __forceinline__ void cp_commit() {
    asm volatile("cp.async.commit_group;" ::: "memory");
}
template <int N>
__device__ __forceinline__ void cp_wait() {
    asm volatile("cp.async.wait_group %0;" :: "n"(N) : "memory");
}
// streaming (evict-first) stores for the write-once attn matrix
__device__ __forceinline__ void st2_cs(float* p, float x, float y) {
    asm volatile("st.global.cs.v2.f32 [%0], {%1, %2};" :: "l"(p), "f"(x), "f"(y) : "memory");
}
__device__ __forceinline__ void st4_cs(float* p, float x, float y, float z, float w) {
    asm volatile("st.global.cs.v4.f32 [%0], {%1, %2, %3, %4};"
                 :: "l"(p), "f"(x), "f"(y), "f"(z), "f"(w) : "memory");
}

// ==========================================================================
// Weight conversion (fp32 [k][n] -> f16 [n][k], all 4 weights in one launch)
// ==========================================================================
__global__ __launch_bounds__(256) void conv_w4(
    const float* __restrict__ W0, const float* __restrict__ W1,
    const float* __restrict__ W2, const float* __restrict__ W3,
    __half* __restrict__ Wh)
{
    __shared__ float t[32][33];
    const int z = blockIdx.z;
    const float* W = (z == 0) ? W0 : (z == 1) ? W1 : (z == 2) ? W2 : W3;
    __half* dst = Wh + (size_t)z * DMODEL * DMODEL;
    const int bx = blockIdx.x * 32;
    const int by = blockIdx.y * 32;
    const int tx = threadIdx.x & 31;
    const int ty = threadIdx.x >> 5;
#pragma unroll
    for (int i = 0; i < 32; i += 8)
        t[ty + i][tx] = W[(size_t)(by + ty + i) * DMODEL + bx + tx];
    __syncthreads();
#pragma unroll
    for (int i = 0; i < 32; i += 8)
        dst[(size_t)(bx + ty + i) * DMODEL + by + tx] = __float2half(t[tx][ty + i]);
}

// ==========================================================================
// HMMA fp16 GEMM with fused fp32->f16 A conversion. 2 CTAs/SM.
// ==========================================================================
#define KC 32
#define NCH (DMODEL / KC)    // 32
#define LDS_STRIDE 40

struct DenseA {
    const float* base;
    __device__ __forceinline__ const float* operator()(int r, int k) const {
        return base + (size_t)r * DMODEL + k;
    }
};
struct CtxA {
    const float* ctx;
    int m0;
    __device__ __forceinline__ const float* operator()(int r, int k) const {
        int m = m0 + r;
        int b = m >> 11, s = m & 2047, h = k >> 6, d = k & 63;
        return ctx + (((size_t)(b * 16 + h)) * S_LEN + s) * DK + d;
    }
};

template <class AF>
__device__ __forceinline__ void gemm_mainloop(
    AF aptr, const __half* Brow,
    __half (*As)[128 * LDS_STRIDE], __half (*Bs)[128 * LDS_STRIDE],
    int tid, int lane, int warp_m, int warp_n, float acc[2][8][4])
{
    const int r0 = tid >> 2, c0 = (tid & 3) * 8;
    const int r1 = r0 + 64;

    {
        const float* a0p = aptr(r0, c0);
        const float* a1p = aptr(r1, c0);
        float4 fa0 = *(const float4*)a0p, fa0b = *(const float4*)(a0p + 4);
        float4 fa1 = *(const float4*)a1p, fa1b = *(const float4*)(a1p + 4);
        uint4 b0 = *(const uint4*)(Brow + (size_t)r0 * DMODEL + c0);
        uint4 b1 = *(const uint4*)(Brow + (size_t)r1 * DMODEL + c0);
        uint4 ua0 = make_uint4(f2h2(fa0.x, fa0.y), f2h2(fa0.z, fa0.w),
                               f2h2(fa0b.x, fa0b.y), f2h2(fa0b.z, fa0b.w));
        uint4 ua1 = make_uint4(f2h2(fa1.x, fa1.y), f2h2(fa1.z, fa1.w),
                               f2h2(fa1b.x, fa1b.y), f2h2(fa1b.z, fa1b.w));
        *(uint4*)(As[0] + r0 * LDS_STRIDE + c0) = ua0;
        *(uint4*)(As[0] + r1 * LDS_STRIDE + c0) = ua1;
        *(uint4*)(Bs[0] + r0 * LDS_STRIDE + c0) = b0;
        *(uint4*)(Bs[0] + r1 * LDS_STRIDE + c0) = b1;
    }
    __syncthreads();

    for (int c = 0; c < NCH; c++) {
        const int cur = c & 1, nxt = cur ^ 1;
        float4 fa0, fa0b, fa1, fa1b;
        uint4 pb0, pb1;
        if (c + 1 < NCH) {
            const int ko = (c + 1) * KC;
            const float* a0p = aptr(r0, ko + c0);
            const float* a1p = aptr(r1, ko + c0);
            fa0 = *(const float4*)a0p; fa0b = *(const float4*)(a0p + 4);
            fa1 = *(const float4*)a1p; fa1b = *(const float4*)(a1p + 4);
            pb0 = *(const uint4*)(Brow + (size_t)r0 * DMODEL + ko + c0);
            pb1 = *(const uint4*)(Brow + (size_t)r1 * DMODEL + ko + c0);
        }

        const uint32_t sa = smem_u32(As[cur]);
        const uint32_t sbm = smem_u32(Bs[cur]);
#pragma unroll
        for (int kk2 = 0; kk2 < 2; kk2++) {
            const int kk = kk2 * 16;
            uint32_t af[2][4];
#pragma unroll
            for (int mi = 0; mi < 2; mi++) {
                uint32_t addr = sa + ((warp_m + mi * 16 + (lane & 15)) * LDS_STRIDE
                                      + kk + (lane >> 4) * 8) * 2;
                ldmx4(af[mi], addr);
            }
            uint32_t bf[8][2];
#pragma unroll
            for (int ni2 = 0; ni2 < 4; ni2++) {
                uint32_t rr[4];
                uint32_t addr = sbm + ((warp_n + ni2 * 16 + (lane & 7) + 8 * ((lane >> 3) & 1))
                                       * LDS_STRIDE + kk + (lane >> 4) * 8) * 2;
                ldmx4(rr, addr);
                bf[2 * ni2][0] = rr[0]; bf[2 * ni2 + 1][0] = rr[1];
                bf[2 * ni2][1] = rr[2]; bf[2 * ni2 + 1][1] = rr[3];
            }
#pragma unroll
            for (int mi = 0; mi < 2; mi++)
#pragma unroll
                for (int ni = 0; ni < 8; ni++)
                    mma16816h(acc[mi][ni], af[mi], bf[ni]);
        }

        if (c + 1 < NCH) {
            uint4 ua0 = make_uint4(f2h2(fa0.x, fa0.y), f2h2(fa0.z, fa0.w),
                                   f2h2(fa0b.x, fa0b.y), f2h2(fa0b.z, fa0b.w));
            uint4 ua1 = make_uint4(f2h2(fa1.x, fa1.y), f2h2(fa1.z, fa1.w),
                                   f2h2(fa1b.x, fa1b.y), f2h2(fa1b.z, fa1b.w));
            *(uint4*)(As[nxt] + r0 * LDS_STRIDE + c0) = ua0;
            *(uint4*)(As[nxt] + r1 * LDS_STRIDE + c0) = ua1;
            *(uint4*)(Bs[nxt] + r0 * LDS_STRIDE + c0) = pb0;
            *(uint4*)(Bs[nxt] + r1 * LDS_STRIDE + c0) = pb1;
        }
        __syncthreads();
    }
}

__global__ __launch_bounds__(256, 2) void gemm_qkv(
    const float* __restrict__ q, const float* __restrict__ k,
    const float* __restrict__ v, const __half* __restrict__ Wh,
    const float* __restrict__ bq, const float* __restrict__ bk,
    const float* __restrict__ bv,
    __half* __restrict__ qhf, __half* __restrict__ khf, __half* __restrict__ vtf)
{
    __shared__ __half As[2][128 * LDS_STRIDE];
    __shared__ __half Bs[2][128 * LDS_STRIDE];

    const int tid = threadIdx.x;
    const int wid = tid >> 5, lane = tid & 31;
    const int z = blockIdx.z;
    const int m0 = blockIdx.y * 128, n0 = blockIdx.x * 128;
    const int warp_m = (wid & 3) * 32;
    const int warp_n = (wid >> 2) * 64;

    const float* X = (z == 0) ? q : (z == 1) ? k : v;
    const __half* Brow = Wh + ((size_t)z * DMODEL + n0) * DMODEL;
    const float* bias = (z == 0) ? bq : (z == 1) ? bk : bv;
    __half* Ch = (z == 0) ? qhf : (z == 1) ? khf : vtf;

    float acc[2][8][4];
#pragma unroll
    for (int mi = 0; mi < 2; mi++)
#pragma unroll
        for (int ni = 0; ni < 8; ni++)
#pragma unroll
            for (int j = 0; j < 4; j++) acc[mi][ni][j] = 0.f;

    DenseA ap{X + (size_t)m0 * DMODEL};
    gemm_mainloop(ap, Brow, As, Bs, tid, lane, warp_m, warp_n, acc);

#pragma unroll
    for (int ni = 0; ni < 8; ni++) {
        const int n = n0 + warp_n + ni * 8 + (lane & 3) * 2;
        const float bv0 = __ldg(&bias[n]);
        const float bv1 = __ldg(&bias[n + 1]);
#pragma unroll
        for (int mi = 0; mi < 2; mi++) {
#pragma unroll
            for (int half = 0; half < 2; half++) {
                const int m = m0 + warp_m + mi * 16 + (lane >> 2) + half * 8;
                float ox = acc[mi][ni][2 * half] + bv0;
                float oy = acc[mi][ni][2 * half + 1] + bv1;
                int b = m >> 11, s = m & 2047;
                int h = n >> 6, d = n & 63;
                if (z < 2) {
                    *(__half2*)&Ch[(((size_t)(b * 16 + h)) * S_LEN + s) * DK + d] =
                        __floats2half2_rn(ox, oy);
                } else {
                    size_t vb = ((size_t)(b * 16 + h) * DK + d) * S_LEN + s;
                    Ch[vb] = __float2half(ox);
                    Ch[vb + S_LEN] = __float2half(oy);
                }
            }
        }
    }
}

__global__ __launch_bounds__(256, 2) void gemm_out(
    const float* __restrict__ ctx, const __half* __restrict__ Wh,
    const float* __restrict__ bias, float* __restrict__ C)
{
    __shared__ __half As[2][128 * LDS_STRIDE];
    __shared__ __half Bs[2][128 * LDS_STRIDE];

    const int tid = threadIdx.x;
    const int wid = tid >> 5, lane = tid & 31;
    const int m0 = blockIdx.y * 128, n0 = blockIdx.x * 128;
    const int warp_m = (wid & 3) * 32;
    const int warp_n = (wid >> 2) * 64;

    const __half* Brow = Wh + (size_t)n0 * DMODEL;

    float acc[2][8][4];
#pragma unroll
    for (int mi = 0; mi < 2; mi++)
#pragma unroll
        for (int ni = 0; ni < 8; ni++)
#pragma unroll
            for (int j = 0; j < 4; j++) acc[mi][ni][j] = 0.f;

    CtxA ap{ctx, m0};
    gemm_mainloop(ap, Brow, As, Bs, tid, lane, warp_m, warp_n, acc);

#pragma unroll
    for (int ni = 0; ni < 8; ni++) {
        const int n = n0 + warp_n + ni * 8 + (lane & 3) * 2;
        const float bv0 = __ldg(&bias[n]);
        const float bv1 = __ldg(&bias[n + 1]);
#pragma unroll
        for (int mi = 0; mi < 2; mi++) {
#pragma unroll
            for (int half = 0; half < 2; half++) {
                const int m = m0 + warp_m + mi * 16 + (lane >> 2) + half * 8;
                *(float2*)&C[(size_t)m * DMODEL + n] =
                    make_float2(acc[mi][ni][2 * half] + bv0,
                                acc[mi][ni][2 * half + 1] + bv1);
            }
        }
    }
}

// ==========================================================================
// Attention pass 1: per-row m, l.  cp.async double-buffered K; 3 CTAs/SM.
// ==========================================================================
#define ATT_STRIDE 72
#define SC_LOG2E 0.18033688011112042f   // log2(e)/sqrt(64)

__global__ __launch_bounds__(256, 3) void attn_pass1(
    const __half* __restrict__ qhf, const __half* __restrict__ khf,
    float* __restrict__ gm, float* __restrict__ gl)
{
    __shared__ __half Qs[128 * ATT_STRIDE];
    __shared__ __half Ks[2][64 * ATT_STRIDE];

    const int tid = threadIdx.x, lane = tid & 31, wid = tid >> 5;
    const int bh = blockIdx.x;
    const int qt = gridDim.y - 1 - blockIdx.y;
    const int i0 = qt * 128;
    const int qw0 = wid * 16;
    const size_t qbase = (size_t)bh * S_LEN * DK;

#pragma unroll
    for (int it = 0; it < 4; it++) {
        int idx = tid + it * 256;
        int r = idx >> 3, g = idx & 7;
        *(uint4*)&Qs[r * ATT_STRIDE + g * 8] =
            *(const uint4*)&qhf[qbase + (size_t)(i0 + r) * DK + g * 8];
    }

    const int ntiles = 2 * qt + 2;
    const int lr = tid >> 2, lg = (tid & 3) * 2;
#pragma unroll
    for (int h = 0; h < 2; h++)
        cp16(smem_u32(&Ks[0][lr * ATT_STRIDE + (lg + h) * 8]),
             &khf[qbase + (size_t)lr * DK + (lg + h) * 8]);
    cp_commit();

    float m2[2] = {-1e30f, -1e30f};
    float l[2] = {0.f, 0.f};
    const uint32_t sQ = smem_u32(Qs);
    const int rg0 = i0 + qw0 + (lane >> 2);

    for (int jt = 0; jt < ntiles; jt++) {
        const int cur = jt & 1;
        if (jt + 1 < ntiles) {
            const int j1 = (jt + 1) * 64;
#pragma unroll
            for (int h = 0; h < 2; h++)
                cp16(smem_u32(&Ks[cur ^ 1][lr * ATT_STRIDE + (lg + h) * 8]),
                     &khf[qbase + (size_t)(j1 + lr) * DK + (lg + h) * 8]);
            cp_commit();
            cp_wait<1>();
        } else {
            cp_wait<0>();
        }
        __syncthreads();

        const int j0 = jt * 64;
        const uint32_t sK = smem_u32(Ks[cur]);

        float sacc[8][4];
#pragma unroll
        for (int ni = 0; ni < 8; ni++)
#pragma unroll
            for (int j = 0; j < 4; j++) sacc[ni][j] = 0.f;

#pragma unroll
        for (int t = 0; t < 4; t++) {
            const int ko = t * 16;
            uint32_t af[4];
            ldmx4(af, sQ + ((qw0 + (lane & 15)) * ATT_STRIDE + ko + (lane >> 4) * 8) * 2);
            uint32_t bf[8][2];
#pragma unroll
            for (int nb = 0; nb < 4; nb++) {
                uint32_t r[4];
                ldmx4(r, sK + ((nb * 16 + (lane & 7) + 8 * ((lane >> 3) & 1)) * ATT_STRIDE
                               + ko + (lane >> 4) * 8) * 2);
                bf[2 * nb][0] = r[0]; bf[2 * nb + 1][0] = r[1];
                bf[2 * nb][1] = r[2]; bf[2 * nb + 1][1] = r[3];
            }
#pragma unroll
            for (int ni = 0; ni < 8; ni++) mma16816h(sacc[ni], af, bf[ni]);
        }

        float mx0 = -1e30f, mx1 = -1e30f;
        const bool masked = (jt >= ntiles - 2);
#pragma unroll
        for (int ni = 0; ni < 8; ni++) {
#pragma unroll
            for (int j = 0; j < 4; j++) sacc[ni][j] *= SC_LOG2E;
            if (masked) {
                int cg = j0 + ni * 8 + (lane & 3) * 2;
                if (cg > rg0)     sacc[ni][0] = -1e30f;
                if (cg + 1 > rg0) sacc[ni][1] = -1e30f;
                if (cg > rg0 + 8)     sacc[ni][2] = -1e30f;
                if (cg + 1 > rg0 + 8) sacc[ni][3] = -1e30f;
            }
            mx0 = fmaxf(mx0, fmaxf(sacc[ni][0], sacc[ni][1]));
            mx1 = fmaxf(mx1, fmaxf(sacc[ni][2], sacc[ni][3]));
        }
#pragma unroll
        for (int o = 1; o < 4; o <<= 1) {
            mx0 = fmaxf(mx0, __shfl_xor_sync(0xffffffffu, mx0, o));
            mx1 = fmaxf(mx1, __shfl_xor_sync(0xffffffffu, mx1, o));
        }
        const float mn0 = fmaxf(m2[0], mx0), mn1 = fmaxf(m2[1], mx1);
        float ts0 = 0.f, ts1 = 0.f;
#pragma unroll
        for (int ni = 0; ni < 8; ni++) {
            ts0 += exp2f(sacc[ni][0] - mn0) + exp2f(sacc[ni][1] - mn0);
            ts1 += exp2f(sacc[ni][2] - mn1) + exp2f(sacc[ni][3] - mn1);
        }
#pragma unroll
        for (int o = 1; o < 4; o <<= 1) {
            ts0 += __shfl_xor_sync(0xffffffffu, ts0, o);
            ts1 += __shfl_xor_sync(0xffffffffu, ts1, o);
        }
        l[0] = l[0] * exp2f(m2[0] - mn0) + ts0;
        l[1] = l[1] * exp2f(m2[1] - mn1) + ts1;
        m2[0] = mn0; m2[1] = mn1;
        __syncthreads();
    }

    if ((lane & 3) == 0) {
        gm[bh * S_LEN + rg0] = m2[0];      gm[bh * S_LEN + rg0 + 8] = m2[1];
        gl[bh * S_LEN + rg0] = l[0];       gl[bh * S_LEN + rg0 + 8] = l[1];
    }
}

// ==========================================================================
// Attention pass 2: P fragments in registers; cp.async K/V double buffer;
// attn = p/l via streaming (st.cs) stores. 2 CTAs/SM.
// ==========================================================================
#define ATT2_SMEM ((128 * ATT_STRIDE + 4 * 64 * ATT_STRIDE) * 2)   // 55296

__global__ __launch_bounds__(256, 2) void attn_pass2(
    const __half* __restrict__ qhf, const __half* __restrict__ khf,
    const __half* __restrict__ vtf,
    const float* __restrict__ gm, const float* __restrict__ gl,
    float* __restrict__ attn, float* __restrict__ ctx)
{
    extern __shared__ __half sh[];
    __half* Qs = sh;                            // [128][72]
    __half* Kb[2] = { sh + 128 * ATT_STRIDE,
                      sh + (128 + 64) * ATT_STRIDE };
    __half* Vb[2] = { sh + (128 + 128) * ATT_STRIDE,
                      sh + (128 + 192) * ATT_STRIDE };

    const int tid = threadIdx.x, lane = tid & 31, wid = tid >> 5;
    const int bh = blockIdx.x;
    const int qt = gridDim.y - 1 - blockIdx.y;
    const int i0 = qt * 128;
    const int qw0 = wid * 16;
    const size_t qbase = (size_t)bh * S_LEN * DK;

#pragma unroll
    for (int it = 0; it < 4; it++) {
        int idx = tid + it * 256;
        int r = idx >> 3, g = idx & 7;
        *(uint4*)&Qs[r * ATT_STRIDE + g * 8] =
            *(const uint4*)&qhf[qbase + (size_t)(i0 + r) * DK + g * 8];
    }

    const int rg0 = i0 + qw0 + (lane >> 2);
    const float mf0 = gm[bh * S_LEN + rg0], mf1 = gm[bh * S_LEN + rg0 + 8];
    const float li0 = 1.f / gl[bh * S_LEN + rg0], li1 = 1.f / gl[bh * S_LEN + rg0 + 8];

    float cacc[8][4];
#pragma unroll
    for (int ni = 0; ni < 8; ni++)
#pragma unroll
        for (int j = 0; j < 4; j++) cacc[ni][j] = 0.f;

    const uint32_t sQ = smem_u32(Qs);
    const int ntiles = 2 * qt + 2;
    const int lr = tid >> 2, lg = (tid & 3) * 2;

    // preload tile 0 (K + V)
#pragma unroll
    for (int h = 0; h < 2; h++) {
        cp16(smem_u32(&Kb[0][lr * ATT_STRIDE + (lg + h) * 8]),
             &khf[qbase + (size_t)lr * DK + (lg + h) * 8]);
        cp16(smem_u32(&Vb[0][lr * ATT_STRIDE + (lg + h) * 8]),
             &vtf[((size_t)bh * DK + lr) * S_LEN + (lg + h) * 8]);
    }
    cp_commit();

    for (int jt = 0; jt < ntiles; jt++) {
        const int cur = jt & 1;
        if (jt + 1 < ntiles) {
            const int j1 = (jt + 1) * 64;
#pragma unroll
            for (int h = 0; h < 2; h++) {
                cp16(smem_u32(&Kb[cur ^ 1][lr * ATT_STRIDE + (lg + h) * 8]),
                     &khf[qbase + (size_t)(j1 + lr) * DK + (lg + h) * 8]);
                cp16(smem_u32(&Vb[cur ^ 1][lr * ATT_STRIDE + (lg + h) * 8]),
                     &vtf[((size_t)bh * DK + lr) * S_LEN + j1 + (lg + h) * 8]);
            }
            cp_commit();
            cp_wait<1>();
        } else {
            cp_wait<0>();
        }
        __syncthreads();

        const int j0 = jt * 64;
        const uint32_t sK = smem_u32(Kb[cur]);
        const uint32_t sV = smem_u32(Vb[cur]);

        // ---- QK^T ----
        float sacc[8][4];
#pragma unroll
        for (int ni = 0; ni < 8; ni++)
#pragma unroll
            for (int j = 0; j < 4; j++) sacc[ni][j] = 0.f;

#pragma unroll
        for (int t = 0; t < 4; t++) {
            const int ko = t * 16;
            uint32_t af[4];
            ldmx4(af, sQ + ((qw0 + (lane & 15)) * ATT_STRIDE + ko + (lane >> 4) * 8) * 2);
            uint32_t bf[8][2];
#pragma unroll
            for (int nb = 0; nb < 4; nb++) {
                uint32_t r[4];
                ldmx4(r, sK + ((nb * 16 + (lane & 7) + 8 * ((lane >> 3) & 1)) * ATT_STRIDE
                               + ko + (lane >> 4) * 8) * 2);
                bf[2 * nb][0] = r[0]; bf[2 * nb + 1][0] = r[1];
                bf[2 * nb][1] = r[2]; bf[2 * nb + 1][1] = r[3];
            }
#pragma unroll
            for (int ni = 0; ni < 8; ni++) mma16816h(sacc[ni], af, bf[ni]);
        }

        // ---- softmax: p fp32 -> streaming attn store + packed P fragments ----
        const bool masked = (jt >= ntiles - 2);
        uint32_t pp[8][2];
#pragma unroll
        for (int ni = 0; ni < 8; ni++) {
            const int c = ni * 8 + (lane & 3) * 2;
            float s0 = sacc[ni][0] * SC_LOG2E, s1 = sacc[ni][1] * SC_LOG2E;
            float s2 = sacc[ni][2] * SC_LOG2E, s3 = sacc[ni][3] * SC_LOG2E;
            if (masked) {
                int cg = j0 + c;
                if (cg > rg0)         s0 = -1e30f;
                if (cg + 1 > rg0)     s1 = -1e30f;
                if (cg > rg0 + 8)     s2 = -1e30f;
                if (cg + 1 > rg0 + 8) s3 = -1e30f;
            }
            float p0 = exp2f(s0 - mf0), p1 = exp2f(s1 - mf0);
            float p2 = exp2f(s2 - mf1), p3 = exp2f(s3 - mf1);
            pp[ni][0] = pack_f16x2(p0, p1);
            pp[ni][1] = pack_f16x2(p2, p3);
            if (attn) {
                st2_cs(&attn[((size_t)bh * S_LEN + rg0) * S_LEN + j0 + c],
                       p0 * li0, p1 * li0);
                st2_cs(&attn[((size_t)bh * S_LEN + rg0 + 8) * S_LEN + j0 + c],
                       p2 * li1, p3 * li1);
            }
        }

        // ---- PV: ctx += P @ V, P fragments from registers ----
#pragma unroll
        for (int t = 0; t < 4; t++) {
            const int ko = t * 16;
            uint32_t af[4] = { pp[2 * t][0], pp[2 * t][1],
                               pp[2 * t + 1][0], pp[2 * t + 1][1] };
            uint32_t bf[8][2];
#pragma unroll
            for (int nb = 0; nb < 4; nb++) {
                uint32_t r[4];
                ldmx4(r, sV + ((nb * 16 + (lane & 7) + 8 * ((lane >> 3) & 1)) * ATT_STRIDE
                               + ko + (lane >> 4) * 8) * 2);
                bf[2 * nb][0] = r[0]; bf[2 * nb + 1][0] = r[1];
                bf[2 * nb][1] = r[2]; bf[2 * nb + 1][1] = r[3];
            }
#pragma unroll
            for (int ni = 0; ni < 8; ni++) mma16816h(cacc[ni], af, bf[ni]);
        }
        __syncthreads();
    }

    // zero-fill the never-visited upper-triangle tiles of attn (streaming)
    if (attn) {
        for (int jt = ntiles; jt < NTILE; jt++) {
            const int j0 = jt * 64;
#pragma unroll
            for (int it = 0; it < 8; it++) {
                int idx = tid + it * 256;
                int r = idx >> 4, c4 = (idx & 15) << 2;
                st4_cs(&attn[((size_t)bh * S_LEN + i0 + r) * S_LEN + j0 + c4],
                       0.f, 0.f, 0.f, 0.f);
            }
        }
    }

    // epilogue: ctx = cacc / l  (cacheable — re-read by gemm_out)
#pragma unroll
    for (int ni = 0; ni < 8; ni++) {
        const int d = ni * 8 + (lane & 3) * 2;
        *(float2*)&ctx[qbase + (size_t)rg0 * DK + d] =
            make_float2(cacc[ni][0] * li0, cacc[ni][1] * li0);
        *(float2*)&ctx[qbase + (size_t)(rg0 + 8) * DK + d] =
            make_float2(cacc[ni][2] * li1, cacc[ni][3] * li1);
    }
}

// ==========================================================================
// host launch
// ==========================================================================
extern "C" void kernel_launch(void* const* d_in, const int* in_sizes, int n_in,
                              void* d_out, int out_size)
{
    const float* q  = (const float*)d_in[0];
    const float* k  = (const float*)d_in[1];
    const float* v  = (const float*)d_in[2];
    const float* wq = (const float*)d_in[4];
    const float* bq = (const float*)d_in[5];
    const float* wk = (const float*)d_in[6];
    const float* bk = (const float*)d_in[7];
    const float* wv = (const float*)d_in[8];
    const float* bv = (const float*)d_in[9];
    const float* wo = (const float*)d_in[10];
    const float* bo = (const float*)d_in[11];

    float *ctx, *gm, *gl;
    __half *wh, *qhf, *khf, *vtf;
    cudaGetSymbolAddress((void**)&ctx, g_ctx);
    cudaGetSymbolAddress((void**)&gm, g_m);
    cudaGetSymbolAddress((void**)&gl, g_l);
    cudaGetSymbolAddress((void**)&wh, g_wh);
    cudaGetSymbolAddress((void**)&qhf, g_qhf);
    cudaGetSymbolAddress((void**)&khf, g_khf);
    cudaGetSymbolAddress((void**)&vtf, g_vtf);

    float* outbuf = (float*)d_out;
    float* out_ptr = nullptr;
    float* attn_ptr = nullptr;
    const long long OUT_N  = (long long)BATCH * S_LEN * DMODEL;
    const long long ATTN_N = (long long)BH * S_LEN * S_LEN;
    long long osz = (long long)out_size;
    if (osz >= OUT_N + ATTN_N)      { out_ptr = outbuf; attn_ptr = outbuf + OUT_N; }
    else if (osz == OUT_N)          { out_ptr = outbuf; }
    else                            { attn_ptr = outbuf; }

    cudaFuncSetAttribute(attn_pass2, cudaFuncAttributeMaxDynamicSharedMemorySize, ATT2_SMEM);

    dim3 wgrid(32, 32, 4);
    conv_w4<<<wgrid, 256>>>(wq, wk, wv, wo, wh);

    dim3 ggrid(DMODEL / 128, MROWS / 128, 3);   // (8, 32, 3)
    gemm_qkv<<<ggrid, 256>>>(q, k, v, wh, bq, bk, bv, qhf, khf, vtf);

    dim3 agrid(BH, S_LEN / 128);                // (32, 16)
    attn_pass1<<<agrid, 256>>>(qhf, khf, gm, gl);
    attn_pass2<<<agrid, 256, ATT2_SMEM>>>(qhf, khf, vtf, gm, gl, attn_ptr, ctx);

    if (out_ptr) {
        dim3 ogrid(DMODEL / 128, MROWS / 128);
        gemm_out<<<ogrid, 256>>>(ctx, wh + 3 * (size_t)DMODEL * DMODEL, bo, out_ptr);
    }
}

// round 14
// speedup vs baseline: 1.0654x; 1.0163x over previous
#include <cuda_runtime.h>
#include <cuda_fp16.h>
#include <cstdint>

#define S_LEN 2048
#define DMODEL 1024
#define NHEADS 16
#define DK 64
#define BATCH 2
#define BH (BATCH * NHEADS)
#define MROWS (BATCH * S_LEN)   // 4096
#define NTILE 32                // 2048/64 key tiles per row

// ---------------- scratch (device globals; no allocation allowed) ----------
__device__ float g_ctx[BH * S_LEN * DK];
__device__ float g_m[BH * S_LEN];           // log2-domain row max
__device__ float g_l[BH * S_LEN];           // row sumexp
__device__ __half g_wh[4 * DMODEL * DMODEL];    // weights [n][k] f16
__device__ __half g_qhf[BH * S_LEN * DK];       // [bh][s][dk]
__device__ __half g_khf[BH * S_LEN * DK];       // [bh][s][dk]
__device__ __half g_vtf[BH * DK * S_LEN];       // [bh][dk][s]  (transposed)

// ---------------- primitives ------------------------------------------------
__device__ __forceinline__ uint32_t smem_u32(const void* p) {
    uint32_t a;
    asm("{ .reg .u64 t; cvta.to.shared.u64 t, %1; cvt.u32.u64 %0, t; }" : "=r"(a) : "l"(p));
    return a;
}
__device__ __forceinline__ void ldmx4(uint32_t* r, uint32_t addr) {
    asm volatile("ldmatrix.sync.aligned.m8n8.x4.shared.b16 {%0,%1,%2,%3}, [%4];"
                 : "=r"(r[0]), "=r"(r[1]), "=r"(r[2]), "=r"(r[3]) : "r"(addr));
}
__device__ __forceinline__ void mma16816h(float* c, const uint32_t* a, const uint32_t* b) {
    asm volatile(
        "mma.sync.aligned.m16n8k16.row.col.f32.f16.f16.f32 "
        "{%0,%1,%2,%3}, {%4,%5,%6,%7}, {%8,%9}, {%0,%1,%2,%3};"
        : "+f"(c[0]), "+f"(c[1]), "+f"(c[2]), "+f"(c[3])
        : "r"(a[0]), "r"(a[1]), "r"(a[2]), "r"(a[3]), "r"(b[0]), "r"(b[1]));
}
__device__ __forceinline__ uint32_t pack_f16x2(float lo, float hi) {
    uint32_t d;
    asm("cvt.rn.f16x2.f32 %0, %1, %2;" : "=r"(d) : "f"(hi), "f"(lo));
    return d;
}
__device__ __forceinline__ uint32_t f2h2(float a, float b) {
    __half2 h = __floats2half2_rn(a, b);
    return *(uint32_t*)&h;
}
__device__ __forceinline__ void cp16(uint32_t saddr, const void* g) {
    asm volatile("cp.async.cg.shared.global [%0], [%1], 16;" :: "r"(saddr), "l"(g));
}
__device__ __forceinline__ void cp_commit() {
    asm volatile("cp.async.commit_group;" ::: "memory");
}
template <int N>
__device__ __forceinline__ void cp_wait() {
    asm volatile("cp.async.wait_group %0;" :: "n"(N) : "memory");
}
// streaming (evict-first) stores for the write-once attn matrix
__device__ __forceinline__ void st2_cs(float* p, float x, float y) {
    asm volatile("st.global.cs.v2.f32 [%0], {%1, %2};" :: "l"(p), "f"(x), "f"(y) : "memory");
}
__device__ __forceinline__ void st4_cs(float* p, float x, float y, float z, float w) {
    asm volatile("st.global.cs.v4.f32 [%0], {%1, %2, %3, %4};"
                 :: "l"(p), "f"(x), "f"(y), "f"(z), "f"(w) : "memory");
}

// ==========================================================================
// Weight conversion (fp32 [k][n] -> f16 [n][k], all 4 weights in one launch)
// ==========================================================================
__global__ __launch_bounds__(256) void conv_w4(
    const float* __restrict__ W0, const float* __restrict__ W1,
    const float* __restrict__ W2, const float* __restrict__ W3,
    __half* __restrict__ Wh)
{
    __shared__ float t[32][33];
    const int z = blockIdx.z;
    const float* W = (z == 0) ? W0 : (z == 1) ? W1 : (z == 2) ? W2 : W3;
    __half* dst = Wh + (size_t)z * DMODEL * DMODEL;
    const int bx = blockIdx.x * 32;
    const int by = blockIdx.y * 32;
    const int tx = threadIdx.x & 31;
    const int ty = threadIdx.x >> 5;
#pragma unroll
    for (int i = 0; i < 32; i += 8)
        t[ty + i][tx] = W[(size_t)(by + ty + i) * DMODEL + bx + tx];
    __syncthreads();
#pragma unroll
    for (int i = 0; i < 32; i += 8)
        dst[(size_t)(bx + ty + i) * DMODEL + by + tx] = __float2half(t[tx][ty + i]);
}

// ==========================================================================
// HMMA fp16 GEMM with fused fp32->f16 A conversion. 2 CTAs/SM.
// ==========================================================================
#define KC 32
#define NCH (DMODEL / KC)    // 32
#define LDS_STRIDE 40

struct DenseA {
    const float* base;
    __device__ __forceinline__ const float* operator()(int r, int k) const {
        return base + (size_t)r * DMODEL + k;
    }
};
struct CtxA {
    const float* ctx;
    int m0;
    __device__ __forceinline__ const float* operator()(int r, int k) const {
        int m = m0 + r;
        int b = m >> 11, s = m & 2047, h = k >> 6, d = k & 63;
        return ctx + (((size_t)(b * 16 + h)) * S_LEN + s) * DK + d;
    }
};

template <class AF>
__device__ __forceinline__ void gemm_mainloop(
    AF aptr, const __half* Brow,
    __half (*As)[128 * LDS_STRIDE], __half (*Bs)[128 * LDS_STRIDE],
    int tid, int lane, int warp_m, int warp_n, float acc[2][8][4])
{
    const int r0 = tid >> 2, c0 = (tid & 3) * 8;
    const int r1 = r0 + 64;

    {
        const float* a0p = aptr(r0, c0);
        const float* a1p = aptr(r1, c0);
        float4 fa0 = *(const float4*)a0p, fa0b = *(const float4*)(a0p + 4);
        float4 fa1 = *(const float4*)a1p, fa1b = *(const float4*)(a1p + 4);
        uint4 b0 = *(const uint4*)(Brow + (size_t)r0 * DMODEL + c0);
        uint4 b1 = *(const uint4*)(Brow + (size_t)r1 * DMODEL + c0);
        uint4 ua0 = make_uint4(f2h2(fa0.x, fa0.y), f2h2(fa0.z, fa0.w),
                               f2h2(fa0b.x, fa0b.y), f2h2(fa0b.z, fa0b.w));
        uint4 ua1 = make_uint4(f2h2(fa1.x, fa1.y), f2h2(fa1.z, fa1.w),
                               f2h2(fa1b.x, fa1b.y), f2h2(fa1b.z, fa1b.w));
        *(uint4*)(As[0] + r0 * LDS_STRIDE + c0) = ua0;
        *(uint4*)(As[0] + r1 * LDS_STRIDE + c0) = ua1;
        *(uint4*)(Bs[0] + r0 * LDS_STRIDE + c0) = b0;
        *(uint4*)(Bs[0] + r1 * LDS_STRIDE + c0) = b1;
    }
    __syncthreads();

    for (int c = 0; c < NCH; c++) {
        const int cur = c & 1, nxt = cur ^ 1;
        float4 fa0, fa0b, fa1, fa1b;
        uint4 pb0, pb1;
        if (c + 1 < NCH) {
            const int ko = (c + 1) * KC;
            const float* a0p = aptr(r0, ko + c0);
            const float* a1p = aptr(r1, ko + c0);
            fa0 = *(const float4*)a0p; fa0b = *(const float4*)(a0p + 4);
            fa1 = *(const float4*)a1p; fa1b = *(const float4*)(a1p + 4);
            pb0 = *(const uint4*)(Brow + (size_t)r0 * DMODEL + ko + c0);
            pb1 = *(const uint4*)(Brow + (size_t)r1 * DMODEL + ko + c0);
        }

        const uint32_t sa = smem_u32(As[cur]);
        const uint32_t sbm = smem_u32(Bs[cur]);
#pragma unroll
        for (int kk2 = 0; kk2 < 2; kk2++) {
            const int kk = kk2 * 16;
            uint32_t af[2][4];
#pragma unroll
            for (int mi = 0; mi < 2; mi++) {
                uint32_t addr = sa + ((warp_m + mi * 16 + (lane & 15)) * LDS_STRIDE
                                      + kk + (lane >> 4) * 8) * 2;
                ldmx4(af[mi], addr);
            }
            uint32_t bf[8][2];
#pragma unroll
            for (int ni2 = 0; ni2 < 4; ni2++) {
                uint32_t rr[4];
                uint32_t addr = sbm + ((warp_n + ni2 * 16 + (lane & 7) + 8 * ((lane >> 3) & 1))
                                       * LDS_STRIDE + kk + (lane >> 4) * 8) * 2;
                ldmx4(rr, addr);
                bf[2 * ni2][0] = rr[0]; bf[2 * ni2 + 1][0] = rr[1];
                bf[2 * ni2][1] = rr[2]; bf[2 * ni2 + 1][1] = rr[3];
            }
#pragma unroll
            for (int mi = 0; mi < 2; mi++)
#pragma unroll
                for (int ni = 0; ni < 8; ni++)
                    mma16816h(acc[mi][ni], af[mi], bf[ni]);
        }

        if (c + 1 < NCH) {
            uint4 ua0 = make_uint4(f2h2(fa0.x, fa0.y), f2h2(fa0.z, fa0.w),
                                   f2h2(fa0b.x, fa0b.y), f2h2(fa0b.z, fa0b.w));
            uint4 ua1 = make_uint4(f2h2(fa1.x, fa1.y), f2h2(fa1.z, fa1.w),
                                   f2h2(fa1b.x, fa1b.y), f2h2(fa1b.z, fa1b.w));
            *(uint4*)(As[nxt] + r0 * LDS_STRIDE + c0) = ua0;
            *(uint4*)(As[nxt] + r1 * LDS_STRIDE + c0) = ua1;
            *(uint4*)(Bs[nxt] + r0 * LDS_STRIDE + c0) = pb0;
            *(uint4*)(Bs[nxt] + r1 * LDS_STRIDE + c0) = pb1;
        }
        __syncthreads();
    }
}

__global__ __launch_bounds__(256, 2) void gemm_qkv(
    const float* __restrict__ q, const float* __restrict__ k,
    const float* __restrict__ v, const __half* __restrict__ Wh,
    const float* __restrict__ bq, const float* __restrict__ bk,
    const float* __restrict__ bv,
    __half* __restrict__ qhf, __half* __restrict__ khf, __half* __restrict__ vtf)
{
    __shared__ __half As[2][128 * LDS_STRIDE];
    __shared__ __half Bs[2][128 * LDS_STRIDE];

    const int tid = threadIdx.x;
    const int wid = tid >> 5, lane = tid & 31;
    const int z = blockIdx.z;
    const int m0 = blockIdx.y * 128, n0 = blockIdx.x * 128;
    const int warp_m = (wid & 3) * 32;
    const int warp_n = (wid >> 2) * 64;

    const float* X = (z == 0) ? q : (z == 1) ? k : v;
    const __half* Brow = Wh + ((size_t)z * DMODEL + n0) * DMODEL;
    const float* bias = (z == 0) ? bq : (z == 1) ? bk : bv;
    __half* Ch = (z == 0) ? qhf : (z == 1) ? khf : vtf;

    float acc[2][8][4];
#pragma unroll
    for (int mi = 0; mi < 2; mi++)
#pragma unroll
        for (int ni = 0; ni < 8; ni++)
#pragma unroll
            for (int j = 0; j < 4; j++) acc[mi][ni][j] = 0.f;

    DenseA ap{X + (size_t)m0 * DMODEL};
    gemm_mainloop(ap, Brow, As, Bs, tid, lane, warp_m, warp_n, acc);

#pragma unroll
    for (int ni = 0; ni < 8; ni++) {
        const int n = n0 + warp_n + ni * 8 + (lane & 3) * 2;
        const float bv0 = __ldg(&bias[n]);
        const float bv1 = __ldg(&bias[n + 1]);
#pragma unroll
        for (int mi = 0; mi < 2; mi++) {
#pragma unroll
            for (int half = 0; half < 2; half++) {
                const int m = m0 + warp_m + mi * 16 + (lane >> 2) + half * 8;
                float ox = acc[mi][ni][2 * half] + bv0;
                float oy = acc[mi][ni][2 * half + 1] + bv1;
                int b = m >> 11, s = m & 2047;
                int h = n >> 6, d = n & 63;
                if (z < 2) {
                    *(__half2*)&Ch[(((size_t)(b * 16 + h)) * S_LEN + s) * DK + d] =
                        __floats2half2_rn(ox, oy);
                } else {
                    size_t vb = ((size_t)(b * 16 + h) * DK + d) * S_LEN + s;
                    Ch[vb] = __float2half(ox);
                    Ch[vb + S_LEN] = __float2half(oy);
                }
            }
        }
    }
}

__global__ __launch_bounds__(256, 2) void gemm_out(
    const float* __restrict__ ctx, const __half* __restrict__ Wh,
    const float* __restrict__ bias, float* __restrict__ C)
{
    __shared__ __half As[2][128 * LDS_STRIDE];
    __shared__ __half Bs[2][128 * LDS_STRIDE];

    const int tid = threadIdx.x;
    const int wid = tid >> 5, lane = tid & 31;
    const int m0 = blockIdx.y * 128, n0 = blockIdx.x * 128;
    const int warp_m = (wid & 3) * 32;
    const int warp_n = (wid >> 2) * 64;

    const __half* Brow = Wh + (size_t)n0 * DMODEL;

    float acc[2][8][4];
#pragma unroll
    for (int mi = 0; mi < 2; mi++)
#pragma unroll
        for (int ni = 0; ni < 8; ni++)
#pragma unroll
            for (int j = 0; j < 4; j++) acc[mi][ni][j] = 0.f;

    CtxA ap{ctx, m0};
    gemm_mainloop(ap, Brow, As, Bs, tid, lane, warp_m, warp_n, acc);

#pragma unroll
    for (int ni = 0; ni < 8; ni++) {
        const int n = n0 + warp_n + ni * 8 + (lane & 3) * 2;
        const float bv0 = __ldg(&bias[n]);
        const float bv1 = __ldg(&bias[n + 1]);
#pragma unroll
        for (int mi = 0; mi < 2; mi++) {
#pragma unroll
            for (int half = 0; half < 2; half++) {
                const int m = m0 + warp_m + mi * 16 + (lane >> 2) + half * 8;
                *(float2*)&C[(size_t)m * DMODEL + n] =
                    make_float2(acc[mi][ni][2 * half] + bv0,
                                acc[mi][ni][2 * half + 1] + bv1);
            }
        }
    }
}

// ==========================================================================
// Attention pass 1: per-row m, l; also zero-fills the upper-triangle attn
// tiles (it has idle store bandwidth). cp.async K double buffer; 3 CTAs/SM.
// ==========================================================================
#define ATT_STRIDE 72
#define SC_LOG2E 0.18033688011112042f   // log2(e)/sqrt(64)

__global__ __launch_bounds__(256, 3) void attn_pass1(
    const __half* __restrict__ qhf, const __half* __restrict__ khf,
    float* __restrict__ gm, float* __restrict__ gl, float* __restrict__ attn)
{
    __shared__ __half Qs[128 * ATT_STRIDE];
    __shared__ __half Ks[2][64 * ATT_STRIDE];

    const int tid = threadIdx.x, lane = tid & 31, wid = tid >> 5;
    const int bh = blockIdx.x;
    const int qt = gridDim.y - 1 - blockIdx.y;
    const int i0 = qt * 128;
    const int qw0 = wid * 16;
    const size_t qbase = (size_t)bh * S_LEN * DK;

#pragma unroll
    for (int it = 0; it < 4; it++) {
        int idx = tid + it * 256;
        int r = idx >> 3, g = idx & 7;
        *(uint4*)&Qs[r * ATT_STRIDE + g * 8] =
            *(const uint4*)&qhf[qbase + (size_t)(i0 + r) * DK + g * 8];
    }

    const int ntiles = 2 * qt + 2;
    const int lr = tid >> 2, lg = (tid & 3) * 2;
#pragma unroll
    for (int h = 0; h < 2; h++)
        cp16(smem_u32(&Ks[0][lr * ATT_STRIDE + (lg + h) * 8]),
             &khf[qbase + (size_t)lr * DK + (lg + h) * 8]);
    cp_commit();

    float m2[2] = {-1e30f, -1e30f};
    float l[2] = {0.f, 0.f};
    const uint32_t sQ = smem_u32(Qs);
    const int rg0 = i0 + qw0 + (lane >> 2);

    // interleave the upper-triangle zero-fill with the mainloop tiles:
    // do one zero tile per compute tile while any remain, rest at the end.
    int zt = ntiles;     // next attn tile column-block to zero

    for (int jt = 0; jt < ntiles; jt++) {
        const int cur = jt & 1;
        if (jt + 1 < ntiles) {
            const int j1 = (jt + 1) * 64;
#pragma unroll
            for (int h = 0; h < 2; h++)
                cp16(smem_u32(&Ks[cur ^ 1][lr * ATT_STRIDE + (lg + h) * 8]),
                     &khf[qbase + (size_t)(j1 + lr) * DK + (lg + h) * 8]);
            cp_commit();
            cp_wait<1>();
        } else {
            cp_wait<0>();
        }
        __syncthreads();

        const int j0 = jt * 64;
        const uint32_t sK = smem_u32(Ks[cur]);

        float sacc[8][4];
#pragma unroll
        for (int ni = 0; ni < 8; ni++)
#pragma unroll
            for (int j = 0; j < 4; j++) sacc[ni][j] = 0.f;

#pragma unroll
        for (int t = 0; t < 4; t++) {
            const int ko = t * 16;
            uint32_t af[4];
            ldmx4(af, sQ + ((qw0 + (lane & 15)) * ATT_STRIDE + ko + (lane >> 4) * 8) * 2);
            uint32_t bf[8][2];
#pragma unroll
            for (int nb = 0; nb < 4; nb++) {
                uint32_t r[4];
                ldmx4(r, sK + ((nb * 16 + (lane & 7) + 8 * ((lane >> 3) & 1)) * ATT_STRIDE
                               + ko + (lane >> 4) * 8) * 2);
                bf[2 * nb][0] = r[0]; bf[2 * nb + 1][0] = r[1];
                bf[2 * nb][1] = r[2]; bf[2 * nb + 1][1] = r[3];
            }
#pragma unroll
            for (int ni = 0; ni < 8; ni++) mma16816h(sacc[ni], af, bf[ni]);
        }

        // interleaved zero-fill of one upper-triangle tile (hides behind MMA)
        if (attn && zt < NTILE) {
            const int zj0 = zt * 64;
#pragma unroll
            for (int it = 0; it < 8; it++) {
                int idx = tid + it * 256;
                int r = idx >> 4, c4 = (idx & 15) << 2;
                st4_cs(&attn[((size_t)bh * S_LEN + i0 + r) * S_LEN + zj0 + c4],
                       0.f, 0.f, 0.f, 0.f);
            }
            zt++;
        }

        float mx0 = -1e30f, mx1 = -1e30f;
        const bool masked = (jt >= ntiles - 2);
#pragma unroll
        for (int ni = 0; ni < 8; ni++) {
#pragma unroll
            for (int j = 0; j < 4; j++) sacc[ni][j] *= SC_LOG2E;
            if (masked) {
                int cg = j0 + ni * 8 + (lane & 3) * 2;
                if (cg > rg0)     sacc[ni][0] = -1e30f;
                if (cg + 1 > rg0) sacc[ni][1] = -1e30f;
                if (cg > rg0 + 8)     sacc[ni][2] = -1e30f;
                if (cg + 1 > rg0 + 8) sacc[ni][3] = -1e30f;
            }
            mx0 = fmaxf(mx0, fmaxf(sacc[ni][0], sacc[ni][1]));
            mx1 = fmaxf(mx1, fmaxf(sacc[ni][2], sacc[ni][3]));
        }
#pragma unroll
        for (int o = 1; o < 4; o <<= 1) {
            mx0 = fmaxf(mx0, __shfl_xor_sync(0xffffffffu, mx0, o));
            mx1 = fmaxf(mx1, __shfl_xor_sync(0xffffffffu, mx1, o));
        }
        const float mn0 = fmaxf(m2[0], mx0), mn1 = fmaxf(m2[1], mx1);
        float ts0 = 0.f, ts1 = 0.f;
#pragma unroll
        for (int ni = 0; ni < 8; ni++) {
            ts0 += exp2f(sacc[ni][0] - mn0) + exp2f(sacc[ni][1] - mn0);
            ts1 += exp2f(sacc[ni][2] - mn1) + exp2f(sacc[ni][3] - mn1);
        }
#pragma unroll
        for (int o = 1; o < 4; o <<= 1) {
            ts0 += __shfl_xor_sync(0xffffffffu, ts0, o);
            ts1 += __shfl_xor_sync(0xffffffffu, ts1, o);
        }
        l[0] = l[0] * exp2f(m2[0] - mn0) + ts0;
        l[1] = l[1] * exp2f(m2[1] - mn1) + ts1;
        m2[0] = mn0; m2[1] = mn1;
        __syncthreads();
    }

    // remaining zero tiles (small-qt CTAs have many; they also finish compute early)
    if (attn) {
        for (; zt < NTILE; zt++) {
            const int zj0 = zt * 64;
#pragma unroll
            for (int it = 0; it < 8; it++) {
                int idx = tid + it * 256;
                int r = idx >> 4, c4 = (idx & 15) << 2;
                st4_cs(&attn[((size_t)bh * S_LEN + i0 + r) * S_LEN + zj0 + c4],
                       0.f, 0.f, 0.f, 0.f);
            }
        }
    }

    if ((lane & 3) == 0) {
        gm[bh * S_LEN + rg0] = m2[0];      gm[bh * S_LEN + rg0 + 8] = m2[1];
        gl[bh * S_LEN + rg0] = l[0];       gl[bh * S_LEN + rg0 + 8] = l[1];
    }
}

// ==========================================================================
// Attention pass 2: P fragments in registers; cp.async K/V double buffer;
// attn = p/l via streaming (st.cs) stores (lower triangle only). 2 CTAs/SM.
// ==========================================================================
#define ATT2_SMEM ((128 * ATT_STRIDE + 4 * 64 * ATT_STRIDE) * 2)   // 55296

__global__ __launch_bounds__(256, 2) void attn_pass2(
    const __half* __restrict__ qhf, const __half* __restrict__ khf,
    const __half* __restrict__ vtf,
    const float* __restrict__ gm, const float* __restrict__ gl,
    float* __restrict__ attn, float* __restrict__ ctx)
{
    extern __shared__ __half sh[];
    __half* Qs = sh;                            // [128][72]
    __half* Kb[2] = { sh + 128 * ATT_STRIDE,
                      sh + (128 + 64) * ATT_STRIDE };
    __half* Vb[2] = { sh + (128 + 128) * ATT_STRIDE,
                      sh + (128 + 192) * ATT_STRIDE };

    const int tid = threadIdx.x, lane = tid & 31, wid = tid >> 5;
    const int bh = blockIdx.x;
    const int qt = gridDim.y - 1 - blockIdx.y;
    const int i0 = qt * 128;
    const int qw0 = wid * 16;
    const size_t qbase = (size_t)bh * S_LEN * DK;

#pragma unroll
    for (int it = 0; it < 4; it++) {
        int idx = tid + it * 256;
        int r = idx >> 3, g = idx & 7;
        *(uint4*)&Qs[r * ATT_STRIDE + g * 8] =
            *(const uint4*)&qhf[qbase + (size_t)(i0 + r) * DK + g * 8];
    }

    const int rg0 = i0 + qw0 + (lane >> 2);
    const float mf0 = gm[bh * S_LEN + rg0], mf1 = gm[bh * S_LEN + rg0 + 8];
    const float li0 = 1.f / gl[bh * S_LEN + rg0], li1 = 1.f / gl[bh * S_LEN + rg0 + 8];

    float cacc[8][4];
#pragma unroll
    for (int ni = 0; ni < 8; ni++)
#pragma unroll
        for (int j = 0; j < 4; j++) cacc[ni][j] = 0.f;

    const uint32_t sQ = smem_u32(Qs);
    const int ntiles = 2 * qt + 2;
    const int lr = tid >> 2, lg = (tid & 3) * 2;

    // preload tile 0 (K + V)
#pragma unroll
    for (int h = 0; h < 2; h++) {
        cp16(smem_u32(&Kb[0][lr * ATT_STRIDE + (lg + h) * 8]),
             &khf[qbase + (size_t)lr * DK + (lg + h) * 8]);
        cp16(smem_u32(&Vb[0][lr * ATT_STRIDE + (lg + h) * 8]),
             &vtf[((size_t)bh * DK + lr) * S_LEN + (lg + h) * 8]);
    }
    cp_commit();

    for (int jt = 0; jt < ntiles; jt++) {
        const int cur = jt & 1;
        if (jt + 1 < ntiles) {
            const int j1 = (jt + 1) * 64;
#pragma unroll
            for (int h = 0; h < 2; h++) {
                cp16(smem_u32(&Kb[cur ^ 1][lr * ATT_STRIDE + (lg + h) * 8]),
                     &khf[qbase + (size_t)(j1 + lr) * DK + (lg + h) * 8]);
                cp16(smem_u32(&Vb[cur ^ 1][lr * ATT_STRIDE + (lg + h) * 8]),
                     &vtf[((size_t)bh * DK + lr) * S_LEN + j1 + (lg + h) * 8]);
            }
            cp_commit();
            cp_wait<1>();
        } else {
            cp_wait<0>();
        }
        __syncthreads();

        const int j0 = jt * 64;
        const uint32_t sK = smem_u32(Kb[cur]);
        const uint32_t sV = smem_u32(Vb[cur]);

        // ---- QK^T ----
        float sacc[8][4];
#pragma unroll
        for (int ni = 0; ni < 8; ni++)
#pragma unroll
            for (int j = 0; j < 4; j++) sacc[ni][j] = 0.f;

#pragma unroll
        for (int t = 0; t < 4; t++) {
            const int ko = t * 16;
            uint32_t af[4];
            ldmx4(af, sQ + ((qw0 + (lane & 15)) * ATT_STRIDE + ko + (lane >> 4) * 8) * 2);
            uint32_t bf[8][2];
#pragma unroll
            for (int nb = 0; nb < 4; nb++) {
                uint32_t r[4];
                ldmx4(r, sK + ((nb * 16 + (lane & 7) + 8 * ((lane >> 3) & 1)) * ATT_STRIDE
                               + ko + (lane >> 4) * 8) * 2);
                bf[2 * nb][0] = r[0]; bf[2 * nb + 1][0] = r[1];
                bf[2 * nb][1] = r[2]; bf[2 * nb + 1][1] = r[3];
            }
#pragma unroll
            for (int ni = 0; ni < 8; ni++) mma16816h(sacc[ni], af, bf[ni]);
        }

        // ---- softmax: p fp32 -> streaming attn store + packed P fragments ----
        const bool masked = (jt >= ntiles - 2);
        uint32_t pp[8][2];
#pragma unroll
        for (int ni = 0; ni < 8; ni++) {
            const int c = ni * 8 + (lane & 3) * 2;
            float s0 = sacc[ni][0] * SC_LOG2E, s1 = sacc[ni][1] * SC_LOG2E;
            float s2 = sacc[ni][2] * SC_LOG2E, s3 = sacc[ni][3] * SC_LOG2E;
            if (masked) {
                int cg = j0 + c;
                if (cg > rg0)         s0 = -1e30f;
                if (cg + 1 > rg0)     s1 = -1e30f;
                if (cg > rg0 + 8)     s2 = -1e30f;
                if (cg + 1 > rg0 + 8) s3 = -1e30f;
            }
            float p0 = exp2f(s0 - mf0), p1 = exp2f(s1 - mf0);
            float p2 = exp2f(s2 - mf1), p3 = exp2f(s3 - mf1);
            pp[ni][0] = pack_f16x2(p0, p1);
            pp[ni][1] = pack_f16x2(p2, p3);
            if (attn) {
                st2_cs(&attn[((size_t)bh * S_LEN + rg0) * S_LEN + j0 + c],
                       p0 * li0, p1 * li0);
                st2_cs(&attn[((size_t)bh * S_LEN + rg0 + 8) * S_LEN + j0 + c],
                       p2 * li1, p3 * li1);
            }
        }

        // ---- PV: ctx += P @ V, P fragments from registers ----
#pragma unroll
        for (int t = 0; t < 4; t++) {
            const int ko = t * 16;
            uint32_t af[4] = { pp[2 * t][0], pp[2 * t][1],
                               pp[2 * t + 1][0], pp[2 * t + 1][1] };
            uint32_t bf[8][2];
#pragma unroll
            for (int nb = 0; nb < 4; nb++) {
                uint32_t r[4];
                ldmx4(r, sV + ((nb * 16 + (lane & 7) + 8 * ((lane >> 3) & 1)) * ATT_STRIDE
                               + ko + (lane >> 4) * 8) * 2);
                bf[2 * nb][0] = r[0]; bf[2 * nb + 1][0] = r[1];
                bf[2 * nb][1] = r[2]; bf[2 * nb + 1][1] = r[3];
            }
#pragma unroll
            for (int ni = 0; ni < 8; ni++) mma16816h(cacc[ni], af, bf[ni]);
        }
        __syncthreads();
    }

    // epilogue: ctx = cacc / l  (cacheable — re-read by gemm_out)
#pragma unroll
    for (int ni = 0; ni < 8; ni++) {
        const int d = ni * 8 + (lane & 3) * 2;
        *(float2*)&ctx[qbase + (size_t)rg0 * DK + d] =
            make_float2(cacc[ni][0] * li0, cacc[ni][1] * li0);
        *(float2*)&ctx[qbase + (size_t)(rg0 + 8) * DK + d] =
            make_float2(cacc[ni][2] * li1, cacc[ni][3] * li1);
    }
}

// ==========================================================================
// host launch
// ==========================================================================
extern "C" void kernel_launch(void* const* d_in, const int* in_sizes, int n_in,
                              void* d_out, int out_size)
{
    const float* q  = (const float*)d_in[0];
    const float* k  = (const float*)d_in[1];
    const float* v  = (const float*)d_in[2];
    const float* wq = (const float*)d_in[4];
    const float* bq = (const float*)d_in[5];
    const float* wk = (const float*)d_in[6];
    const float* bk = (const float*)d_in[7];
    const float* wv = (const float*)d_in[8];
    const float* bv = (const float*)d_in[9];
    const float* wo = (const float*)d_in[10];
    const float* bo = (const float*)d_in[11];

    float *ctx, *gm, *gl;
    __half *wh, *qhf, *khf, *vtf;
    cudaGetSymbolAddress((void**)&ctx, g_ctx);
    cudaGetSymbolAddress((void**)&gm, g_m);
    cudaGetSymbolAddress((void**)&gl, g_l);
    cudaGetSymbolAddress((void**)&wh, g_wh);
    cudaGetSymbolAddress((void**)&qhf, g_qhf);
    cudaGetSymbolAddress((void**)&khf, g_khf);
    cudaGetSymbolAddress((void**)&vtf, g_vtf);

    float* outbuf = (float*)d_out;
    float* out_ptr = nullptr;
    float* attn_ptr = nullptr;
    const long long OUT_N  = (long long)BATCH * S_LEN * DMODEL;
    const long long ATTN_N = (long long)BH * S_LEN * S_LEN;
    long long osz = (long long)out_size;
    if (osz >= OUT_N + ATTN_N)      { out_ptr = outbuf; attn_ptr = outbuf + OUT_N; }
    else if (osz == OUT_N)          { out_ptr = outbuf; }
    else                            { attn_ptr = outbuf; }

    cudaFuncSetAttribute(attn_pass2, cudaFuncAttributeMaxDynamicSharedMemorySize, ATT2_SMEM);

    dim3 wgrid(32, 32, 4);
    conv_w4<<<wgrid, 256>>>(wq, wk, wv, wo, wh);

    dim3 ggrid(DMODEL / 128, MROWS / 128, 3);   // (8, 32, 3)
    gemm_qkv<<<ggrid, 256>>>(q, k, v, wh, bq, bk, bv, qhf, khf, vtf);

    dim3 agrid(BH, S_LEN / 128);                // (32, 16)
    attn_pass1<<<agrid, 256>>>(qhf, khf, gm, gl, attn_ptr);
    attn_pass2<<<agrid, 256, ATT2_SMEM>>>(qhf, khf, vtf, gm, gl, attn_ptr, ctx);

    if (out_ptr) {
        dim3 ogrid(DMODEL / 128, MROWS / 128);
        gemm_out<<<ogrid, 256>>>(ctx, wh + 3 * (size_t)DMODEL * DMODEL, bo, out_ptr);
    }
}